// round 6
// baseline (speedup 1.0000x reference)
#include <cuda_runtime.h>
#include <math.h>

#define B_   32
#define T_   512
#define IND  512
#define U_   1024
#define G4   4096   // 4*U
#define NBLK 128
#define NTHR 512

// ---------------- scratch (static device globals; no allocs allowed) ----------
__device__ __align__(16) float g_xproj[(size_t)B_ * T_ * G4];  // 256 MB [t*B+b][4U]
__device__ __align__(16) float g_hd[2][U_ * B_ * 2];           // dup h: [u][b] -> (h,h)
__device__ unsigned g_count;
__device__ unsigned g_gen;

// ---------------- init: zero dup-h0 every launch (graph replays) --------------
__global__ void init_state() {
    int i = blockIdx.x * blockDim.x + threadIdx.x;
    if (i < U_ * B_ * 2) g_hd[0][i] = 0.f;
}

#define FMA2(acc, a, b) \
    asm("fma.rn.f32x2 %0, %1, %2, %0;" : "+l"(acc) : "l"(a), "l"(b))
#define DUP32(dst, src) \
    asm("mov.b64 %0, {%1, %1};" : "=l"(dst) : "r"(src))
#define UNPK(lo, hi, v) \
    asm("mov.b64 {%0, %1}, %2;" : "=r"(lo), "=r"(hi) : "l"(v))

// ---------------- Kernel 1: x_proj = data @ Wx + b (FFMA2 mainloop) -----------
// Output layout: g_xproj[(t*B + b)][4U]  (contiguous per timestep)
__global__ __launch_bounds__(256) void gemm_xproj(
    const float* __restrict__ A, const float* __restrict__ Bw,
    const float* __restrict__ bias)
{
    const int K = IND, N = G4;
    __shared__ float As[16][132];
    __shared__ float Bs[16][128];

    int tid = threadIdx.x;
    int bm = blockIdx.y * 128;
    int bn = blockIdx.x * 128;

    int ty = tid >> 4;
    int tx = tid & 15;

    int arow = tid >> 2;
    int acol = (tid & 3) * 4;
    int brow = tid >> 5;
    int bcol = (tid & 31) * 4;

    const float* Aptr = A + (size_t)(bm + arow) * K + acol;
    const float* Bptr = Bw + (size_t)brow * N + bn + bcol;

    unsigned long long acc2[8][4];
    #pragma unroll
    for (int i = 0; i < 8; i++)
        #pragma unroll
        for (int j = 0; j < 4; j++) acc2[i][j] = 0ULL;

    for (int k0 = 0; k0 < K; k0 += 16) {
        float4 a0 = *(const float4*)(Aptr);
        float4 a1 = *(const float4*)(Aptr + (size_t)64 * K);
        float4 b0 = *(const float4*)(Bptr);
        float4 b1 = *(const float4*)(Bptr + (size_t)8 * N);

        As[acol + 0][arow] = a0.x; As[acol + 1][arow] = a0.y;
        As[acol + 2][arow] = a0.z; As[acol + 3][arow] = a0.w;
        As[acol + 0][arow + 64] = a1.x; As[acol + 1][arow + 64] = a1.y;
        As[acol + 2][arow + 64] = a1.z; As[acol + 3][arow + 64] = a1.w;
        *(float4*)&Bs[brow][bcol]     = b0;
        *(float4*)&Bs[brow + 8][bcol] = b1;
        __syncthreads();

        #pragma unroll
        for (int kk = 0; kk < 16; kk++) {
            float a[8];
            *(float4*)&a[0] = *(const float4*)&As[kk][ty * 8];
            *(float4*)&a[4] = *(const float4*)&As[kk][ty * 8 + 4];
            ulonglong2 bA = *(const ulonglong2*)&Bs[kk][tx * 8];
            ulonglong2 bB = *(const ulonglong2*)&Bs[kk][tx * 8 + 4];
            #pragma unroll
            for (int i = 0; i < 8; i++) {
                unsigned long long ad;
                DUP32(ad, __float_as_uint(a[i]));
                FMA2(acc2[i][0], ad, bA.x);
                FMA2(acc2[i][1], ad, bA.y);
                FMA2(acc2[i][2], ad, bB.x);
                FMA2(acc2[i][3], ad, bB.y);
            }
        }
        __syncthreads();
        Aptr += 16;
        Bptr += (size_t)16 * N;
    }

    float bv[8];
    #pragma unroll
    for (int j = 0; j < 8; j++) bv[j] = bias[bn + tx * 8 + j];

    #pragma unroll
    for (int i = 0; i < 8; i++) {
        float c[8];
        #pragma unroll
        for (int j = 0; j < 4; j++) {
            unsigned lo, hi;
            UNPK(lo, hi, acc2[i][j]);
            c[2 * j]     = __uint_as_float(lo) + bv[2 * j];
            c[2 * j + 1] = __uint_as_float(hi) + bv[2 * j + 1];
        }
        int m = bm + ty * 8 + i;            // data row = b*T + t
        int bb = m >> 9;                    // batch
        int tt = m & 511;                   // timestep
        float* crow = g_xproj + (size_t)(tt * B_ + bb) * N + bn + tx * 8;
        *(float4*)crow       = make_float4(c[0], c[1], c[2], c[3]);
        *(float4*)(crow + 4) = make_float4(c[4], c[5], c[6], c[7]);
    }
}

// ---------------- Kernel 2: persistent LSTM recurrence ------------------------
__device__ __forceinline__ float sigmoidf_(float x) {
    return 1.f / (1.f + __expf(-x));
}
__device__ __forceinline__ float tanhf_(float x) {
    // tanh(x) = 2*sigmoid(2x) - 1, via fast ex2 path
    return 2.f / (1.f + __expf(-2.f * x)) - 1.f;
}

extern __shared__ float smem_dyn[];

// 128 blocks x 512 threads (1/SM, all resident). Block owns 8 units x 4 gates
// = 32 Wh columns pinned in smem (128 KB). Warp w (0..15) reduces K-chunk
// [w*64, +64). Lane: g = lane&3 (gate), tb = lane>>2 (4-batch group).
// h is stored DUPLICATED in global ((h,h) pairs) so the inner loop consumes
// 64-bit h operands directly: 2 LDG.128 + 2 LDS.128 + 16 FFMA2 per k.
__global__ __launch_bounds__(NTHR) void lstm_persistent(
    const float* __restrict__ Wh,   // [1024][4096]
    float* __restrict__ out)        // [32][512][1024]
{
    float* ws   = smem_dyn;                  // [1024][32]  128 KB
    float* part = smem_dyn + U_ * 32;        // [16*4*8][36] 72 KB

    const int tid  = threadIdx.x;
    const int w    = tid >> 5;               // 0..15
    const int lane = tid & 31;
    const int g    = lane & 3;
    const int tb   = lane >> 2;
    const int u0   = blockIdx.x * 8;

    // ---- load this block's Wh slice into smem (once) ----
    for (int idx = tid; idx < U_ * 8; idx += NTHR) {   // float4 granules
        int k  = idx >> 3;
        int r  = idx & 7;
        int g2 = r >> 1;
        int hf = r & 1;
        float4 v = *(const float4*)(Wh + (size_t)k * G4 + g2 * U_ + u0 + hf * 4);
        *(float4*)&ws[k * 32 + g2 * 8 + hf * 4] = v;
    }

    const int eb = (tid >> 3) & 31;          // epilogue batch (tid<256 active)
    const int eu = tid & 7;                  // epilogue unit
    float c_reg = 0.f;

    unsigned my_gen = *(volatile unsigned*)&g_gen;
    __syncthreads();

    const float* wsp_base = ws + (size_t)(w * 64) * 32 + g * 8;

    for (int t = 0; t < T_; t++) {
        const float* __restrict__ hd_in = g_hd[t & 1];
        float*       __restrict__ hd_out = g_hd[(t + 1) & 1];

        // prefetch epilogue x_proj (contiguous per-t slab) early
        float xpv0, xpv1, xpv2, xpv3;
        if (tid < 256) {
            const float* xp = g_xproj + ((size_t)t * B_ + eb) * G4 + u0 + eu;
            xpv0 = __ldg(xp);
            xpv1 = __ldg(xp + U_);
            xpv2 = __ldg(xp + 2 * U_);
            xpv3 = __ldg(xp + 3 * U_);
        }

        unsigned long long acc2[4][4];   // [unit-pair][batch]
        #pragma unroll
        for (int i = 0; i < 4; i++)
            #pragma unroll
            for (int j = 0; j < 4; j++) acc2[i][j] = 0ULL;

        const float* wsp = wsp_base;
        const float* hp  = hd_in + ((size_t)(w * 64) * B_ + tb * 4) * 2;

        #pragma unroll 8
        for (int kk = 0; kk < 64; kk++) {
            ulonglong2 wA = *(const ulonglong2*)(wsp);       // units 0-3
            ulonglong2 wB = *(const ulonglong2*)(wsp + 4);   // units 4-7
            ulonglong2 hA = __ldcg((const ulonglong2*)hp);       // b0,b1 dup
            ulonglong2 hB = __ldcg((const ulonglong2*)(hp + 4)); // b2,b3 dup

            FMA2(acc2[0][0], wA.x, hA.x); FMA2(acc2[0][1], wA.x, hA.y);
            FMA2(acc2[0][2], wA.x, hB.x); FMA2(acc2[0][3], wA.x, hB.y);
            FMA2(acc2[1][0], wA.y, hA.x); FMA2(acc2[1][1], wA.y, hA.y);
            FMA2(acc2[1][2], wA.y, hB.x); FMA2(acc2[1][3], wA.y, hB.y);
            FMA2(acc2[2][0], wB.x, hA.x); FMA2(acc2[2][1], wB.x, hA.y);
            FMA2(acc2[2][2], wB.x, hB.x); FMA2(acc2[2][3], wB.x, hB.y);
            FMA2(acc2[3][0], wB.y, hA.x); FMA2(acc2[3][1], wB.y, hA.y);
            FMA2(acc2[3][2], wB.y, hB.x); FMA2(acc2[3][3], wB.y, hB.y);

            wsp += 32;
            hp  += 64;
        }

        // publish partials: part[(w*4+g)*8 + u][36]
        #pragma unroll
        for (int u2 = 0; u2 < 4; u2++) {
            float lo[4], hi[4];
            #pragma unroll
            for (int j = 0; j < 4; j++) {
                unsigned l32, h32;
                UNPK(l32, h32, acc2[u2][j]);
                lo[j] = __uint_as_float(l32);
                hi[j] = __uint_as_float(h32);
            }
            *(float4*)&part[(((w * 4 + g) * 8) + 2 * u2)     * 36 + tb * 4] =
                make_float4(lo[0], lo[1], lo[2], lo[3]);
            *(float4*)&part[(((w * 4 + g) * 8) + 2 * u2 + 1) * 36 + tb * 4] =
                make_float4(hi[0], hi[1], hi[2], hi[3]);
        }
        __syncthreads();

        // ---- epilogue: threads 0..255, thread = (eb, eu) ----
        if (tid < 256) {
            float gate[4];
            #pragma unroll
            for (int g2 = 0; g2 < 4; g2++) {
                float s = 0.f;
                #pragma unroll
                for (int w2 = 0; w2 < 16; w2++)
                    s += part[(((w2 * 4 + g2) * 8) + eu) * 36 + eb];
                gate[g2] = s;
            }
            gate[0] += xpv0;
            gate[1] += xpv1;
            gate[2] += xpv2;
            gate[3] += xpv3;

            float ig = sigmoidf_(gate[0]);
            float fg = sigmoidf_(gate[1]);
            float gv = tanhf_(gate[2]);
            float og = sigmoidf_(gate[3]);

            c_reg = fg * c_reg + ig * gv;
            float h = og * tanhf_(c_reg);

            *(float2*)(hd_out + ((size_t)(u0 + eu) * B_ + eb) * 2) =
                make_float2(h, h);
            out[((size_t)eb * T_ + t) * U_ + u0 + eu] = h;
        }

        // ---- grid barrier ----
        __syncthreads();
        if (tid == 0) {
            __threadfence();
            if (atomicAdd(&g_count, 1u) == NBLK - 1) {
                atomicExch(&g_count, 0u);
                __threadfence();
                atomicAdd(&g_gen, 1u);
            } else {
                while (*(volatile unsigned*)&g_gen == my_gen) {}
            }
            my_gen++;
        }
        __syncthreads();
    }
}

// ---------------- launch ------------------------------------------------------
extern "C" void kernel_launch(void* const* d_in, const int* in_sizes, int n_in,
                              void* d_out, int out_size) {
    const float* data = (const float*)d_in[0];   // [32,512,512]
    const float* Wx   = (const float*)d_in[1];   // [512,4096]
    const float* Wh   = (const float*)d_in[2];   // [1024,4096]
    const float* bias = (const float*)d_in[3];   // [4096]
    float* out = (float*)d_out;                  // [32,512,1024]

    const int smem_bytes =
        (U_ * 32 + 16 * 4 * 8 * 36) * (int)sizeof(float);   // 128K + 72K = 200K
    cudaFuncSetAttribute(lstm_persistent,
                         cudaFuncAttributeMaxDynamicSharedMemorySize, smem_bytes);

    init_state<<<64, 1024>>>();

    dim3 grid(G4 / 128, (B_ * T_) / 128);        // 32 x 128
    gemm_xproj<<<grid, 256>>>(data, Wx, bias);

    lstm_persistent<<<NBLK, NTHR, smem_bytes>>>(Wh, out);
}

// round 8
// speedup vs baseline: 1.5347x; 1.5347x over previous
#include <cuda_runtime.h>
#include <math.h>

#define B_   32
#define T_   512
#define IND  512
#define U_   1024
#define G4   4096   // 4*U
#define NBLK 128
#define NTHR 512

// ---------------- scratch (static device globals; no allocs allowed) ----------
__device__ __align__(16) float g_xproj[(size_t)B_ * T_ * G4];  // 256 MB [b*T+t][4U]
__device__ __align__(16) float g_h[2][U_ * B_];                // ping-pong hT: [u][b]
__device__ unsigned g_count;
__device__ unsigned g_gen;

// ---------------- init: zero h0 every launch (graph replays) ------------------
__global__ void init_state() {
    int i = blockIdx.x * blockDim.x + threadIdx.x;
    if (i < U_ * B_) g_h[0][i] = 0.f;
}

#define FMA2(acc, a, b) \
    asm("fma.rn.f32x2 %0, %1, %2, %0;" : "+l"(acc) : "l"(a), "l"(b))
#define DUP32(dst, src) \
    asm("mov.b64 %0, {%1, %1};" : "=l"(dst) : "r"(src))
#define UNPK(lo, hi, v) \
    asm("mov.b64 {%0, %1}, %2;" : "=r"(lo), "=r"(hi) : "l"(v))

// ---------------- Kernel 1: x_proj = data @ Wx + b (FFMA2 mainloop) -----------
__global__ __launch_bounds__(256) void gemm_xproj(
    const float* __restrict__ A, const float* __restrict__ Bw,
    const float* __restrict__ bias)
{
    const int K = IND, N = G4;
    __shared__ float As[16][132];
    __shared__ float Bs[16][128];

    int tid = threadIdx.x;
    int bm = blockIdx.y * 128;
    int bn = blockIdx.x * 128;

    int ty = tid >> 4;
    int tx = tid & 15;

    int arow = tid >> 2;
    int acol = (tid & 3) * 4;
    int brow = tid >> 5;
    int bcol = (tid & 31) * 4;

    const float* Aptr = A + (size_t)(bm + arow) * K + acol;
    const float* Bptr = Bw + (size_t)brow * N + bn + bcol;

    unsigned long long acc2[8][4];
    #pragma unroll
    for (int i = 0; i < 8; i++)
        #pragma unroll
        for (int j = 0; j < 4; j++) acc2[i][j] = 0ULL;

    for (int k0 = 0; k0 < K; k0 += 16) {
        float4 a0 = *(const float4*)(Aptr);
        float4 a1 = *(const float4*)(Aptr + (size_t)64 * K);
        float4 b0 = *(const float4*)(Bptr);
        float4 b1 = *(const float4*)(Bptr + (size_t)8 * N);

        As[acol + 0][arow] = a0.x; As[acol + 1][arow] = a0.y;
        As[acol + 2][arow] = a0.z; As[acol + 3][arow] = a0.w;
        As[acol + 0][arow + 64] = a1.x; As[acol + 1][arow + 64] = a1.y;
        As[acol + 2][arow + 64] = a1.z; As[acol + 3][arow + 64] = a1.w;
        *(float4*)&Bs[brow][bcol]     = b0;
        *(float4*)&Bs[brow + 8][bcol] = b1;
        __syncthreads();

        #pragma unroll
        for (int kk = 0; kk < 16; kk++) {
            float a[8];
            *(float4*)&a[0] = *(const float4*)&As[kk][ty * 8];
            *(float4*)&a[4] = *(const float4*)&As[kk][ty * 8 + 4];
            ulonglong2 bA = *(const ulonglong2*)&Bs[kk][tx * 8];
            ulonglong2 bB = *(const ulonglong2*)&Bs[kk][tx * 8 + 4];
            #pragma unroll
            for (int i = 0; i < 8; i++) {
                unsigned long long ad;
                DUP32(ad, __float_as_uint(a[i]));
                FMA2(acc2[i][0], ad, bA.x);
                FMA2(acc2[i][1], ad, bA.y);
                FMA2(acc2[i][2], ad, bB.x);
                FMA2(acc2[i][3], ad, bB.y);
            }
        }
        __syncthreads();
        Aptr += 16;
        Bptr += (size_t)16 * N;
    }

    float bv[8];
    #pragma unroll
    for (int j = 0; j < 8; j++) bv[j] = bias[bn + tx * 8 + j];

    #pragma unroll
    for (int i = 0; i < 8; i++) {
        float c[8];
        #pragma unroll
        for (int j = 0; j < 4; j++) {
            unsigned lo, hi;
            UNPK(lo, hi, acc2[i][j]);
            c[2 * j]     = __uint_as_float(lo) + bv[2 * j];
            c[2 * j + 1] = __uint_as_float(hi) + bv[2 * j + 1];
        }
        float* crow = g_xproj + (size_t)(bm + ty * 8 + i) * N + bn + tx * 8;
        *(float4*)crow       = make_float4(c[0], c[1], c[2], c[3]);
        *(float4*)(crow + 4) = make_float4(c[4], c[5], c[6], c[7]);
    }
}

// ---------------- Kernel 2: persistent LSTM recurrence ------------------------
__device__ __forceinline__ float sigmoidf_(float x) {
    return 1.f / (1.f + __expf(-x));
}
__device__ __forceinline__ float tanhf_(float x) {
    return 2.f / (1.f + __expf(-2.f * x)) - 1.f;
}

extern __shared__ float smem_dyn[];

// 128 blocks x 512 threads (1/SM, all resident; <=128 regs/thread enforced by
// construction). Block owns 8 units x 4 gates = 32 Wh columns pinned in smem.
// Warp w (0..15) reduces K-chunk [w*64,+64). Lane: g = lane&3 (gate),
// tb = lane>>2 (4-batch group). Explicit 2-stage h prefetch, depth 4 k.
__global__ __launch_bounds__(NTHR) void lstm_persistent(
    const float* __restrict__ Wh,   // [1024][4096]
    float* __restrict__ out)        // [32][512][1024]
{
    float* ws   = smem_dyn;                  // [1024][32]  128 KB
    float* part = smem_dyn + U_ * 32;        // [16*4*8][36] 72 KB

    const int tid  = threadIdx.x;
    const int w    = tid >> 5;               // 0..15
    const int lane = tid & 31;
    const int g    = lane & 3;
    const int tb   = lane >> 2;
    const int u0   = blockIdx.x * 8;

    // ---- load this block's Wh slice into smem (once) ----
    for (int idx = tid; idx < U_ * 8; idx += NTHR) {   // float4 granules
        int k  = idx >> 3;
        int r  = idx & 7;
        int g2 = r >> 1;
        int hf = r & 1;
        float4 v = *(const float4*)(Wh + (size_t)k * G4 + g2 * U_ + u0 + hf * 4);
        *(float4*)&ws[k * 32 + g2 * 8 + hf * 4] = v;
    }

    const int eb = (tid >> 3) & 31;          // epilogue batch (tid<256 active)
    const int eu = tid & 7;                  // epilogue unit
    float c_reg = 0.f;

    unsigned my_gen = *(volatile unsigned*)&g_gen;
    __syncthreads();

    const float* wsp_base = ws + (size_t)(w * 64) * 32 + g * 8;

    for (int t = 0; t < T_; t++) {
        const float* __restrict__ h_in = g_h[t & 1];
        float* __restrict__ h_out      = g_h[(t + 1) & 1];

        // prefetch epilogue x_proj early (hides DRAM latency under compute)
        float xpv0, xpv1, xpv2, xpv3;
        if (tid < 256) {
            const float* xp = g_xproj + ((size_t)eb * T_ + t) * G4 + u0 + eu;
            xpv0 = __ldg(xp);
            xpv1 = __ldg(xp + U_);
            xpv2 = __ldg(xp + 2 * U_);
            xpv3 = __ldg(xp + 3 * U_);
        }

        unsigned long long acc2[4][4];   // [unit-pair][batch]
        #pragma unroll
        for (int i = 0; i < 4; i++)
            #pragma unroll
            for (int j = 0; j < 4; j++) acc2[i][j] = 0ULL;

        const float* wsp = wsp_base;
        const float4* hp = (const float4*)(h_in + (w * 64) * B_) + tb;

        // 2-stage software pipeline, 4-k groups (16 regs of h in flight)
        float4 hbuf[4];
        #pragma unroll
        for (int i = 0; i < 4; i++) hbuf[i] = __ldcg(hp + i * 8);

        #pragma unroll 2
        for (int kg = 0; kg < 16; kg++) {          // 16 groups of 4 k
            float4 hnext[4];
            if (kg < 15) {
                #pragma unroll
                for (int i = 0; i < 4; i++)
                    hnext[i] = __ldcg(hp + (kg + 1) * 32 + i * 8);
            }
            #pragma unroll
            for (int kk = 0; kk < 4; kk++) {
                ulonglong2 wA = *(const ulonglong2*)(wsp + kk * 32);
                ulonglong2 wB = *(const ulonglong2*)(wsp + kk * 32 + 4);
                float4 hv = hbuf[kk];
                unsigned long long hd0, hd1, hd2, hd3;
                DUP32(hd0, __float_as_uint(hv.x));
                DUP32(hd1, __float_as_uint(hv.y));
                DUP32(hd2, __float_as_uint(hv.z));
                DUP32(hd3, __float_as_uint(hv.w));

                FMA2(acc2[0][0], wA.x, hd0); FMA2(acc2[0][1], wA.x, hd1);
                FMA2(acc2[0][2], wA.x, hd2); FMA2(acc2[0][3], wA.x, hd3);
                FMA2(acc2[1][0], wA.y, hd0); FMA2(acc2[1][1], wA.y, hd1);
                FMA2(acc2[1][2], wA.y, hd2); FMA2(acc2[1][3], wA.y, hd3);
                FMA2(acc2[2][0], wB.x, hd0); FMA2(acc2[2][1], wB.x, hd1);
                FMA2(acc2[2][2], wB.x, hd2); FMA2(acc2[2][3], wB.x, hd3);
                FMA2(acc2[3][0], wB.y, hd0); FMA2(acc2[3][1], wB.y, hd1);
                FMA2(acc2[3][2], wB.y, hd2); FMA2(acc2[3][3], wB.y, hd3);
            }
            #pragma unroll
            for (int i = 0; i < 4; i++) hbuf[i] = hnext[i];
            wsp += 4 * 32;
        }

        // publish partials: part[(w*4+g)*8 + u][36]
        #pragma unroll
        for (int u2 = 0; u2 < 4; u2++) {
            float lo[4], hi[4];
            #pragma unroll
            for (int j = 0; j < 4; j++) {
                unsigned l32, h32;
                UNPK(l32, h32, acc2[u2][j]);
                lo[j] = __uint_as_float(l32);
                hi[j] = __uint_as_float(h32);
            }
            *(float4*)&part[(((w * 4 + g) * 8) + 2 * u2)     * 36 + tb * 4] =
                make_float4(lo[0], lo[1], lo[2], lo[3]);
            *(float4*)&part[(((w * 4 + g) * 8) + 2 * u2 + 1) * 36 + tb * 4] =
                make_float4(hi[0], hi[1], hi[2], hi[3]);
        }
        __syncthreads();

        // ---- epilogue: threads 0..255, thread = (eb, eu) ----
        if (tid < 256) {
            float gate[4];
            #pragma unroll
            for (int g2 = 0; g2 < 4; g2++) {
                float s = 0.f;
                #pragma unroll
                for (int w2 = 0; w2 < 16; w2++)
                    s += part[(((w2 * 4 + g2) * 8) + eu) * 36 + eb];
                gate[g2] = s;
            }
            gate[0] += xpv0;
            gate[1] += xpv1;
            gate[2] += xpv2;
            gate[3] += xpv3;

            float ig = sigmoidf_(gate[0]);
            float fg = sigmoidf_(gate[1]);
            float gv = tanhf_(gate[2]);
            float og = sigmoidf_(gate[3]);

            c_reg = fg * c_reg + ig * gv;
            float h = og * tanhf_(c_reg);

            h_out[(u0 + eu) * B_ + eb] = h;
            out[((size_t)eb * T_ + t) * U_ + u0 + eu] = h;
        }

        // ---- grid barrier (R4-proven scheme) ----
        __syncthreads();
        if (tid == 0) {
            __threadfence();
            if (atomicAdd(&g_count, 1u) == NBLK - 1) {
                atomicExch(&g_count, 0u);
                __threadfence();
                atomicAdd(&g_gen, 1u);
            } else {
                while (*(volatile unsigned*)&g_gen == my_gen) {}
            }
            my_gen++;
        }
        __syncthreads();
    }
}

// ---------------- launch ------------------------------------------------------
extern "C" void kernel_launch(void* const* d_in, const int* in_sizes, int n_in,
                              void* d_out, int out_size) {
    const float* data = (const float*)d_in[0];   // [32,512,512]
    const float* Wx   = (const float*)d_in[1];   // [512,4096]
    const float* Wh   = (const float*)d_in[2];   // [1024,4096]
    const float* bias = (const float*)d_in[3];   // [4096]
    float* out = (float*)d_out;                  // [32,512,1024]

    const int smem_bytes =
        (U_ * 32 + 16 * 4 * 8 * 36) * (int)sizeof(float);   // 128K + 72K = 200K
    cudaFuncSetAttribute(lstm_persistent,
                         cudaFuncAttributeMaxDynamicSharedMemorySize, smem_bytes);

    init_state<<<32, 1024>>>();

    dim3 grid(G4 / 128, (B_ * T_) / 128);        // 32 x 128
    gemm_xproj<<<grid, 256>>>(data, Wx, bias);

    lstm_persistent<<<NBLK, NTHR, smem_bytes>>>(Wh, out);
}